// round 13
// baseline (speedup 1.0000x reference)
#include <cuda_runtime.h>
#include <cuda_fp16.h>
#include <cstdint>

// VQ argmin: 32768 positions x 1024 codewords, C=256.
// inputs [32,256,32,32] f32, embed [256,1024] f32.
// out = concat(quantize_st [8388608], loss [1], onehot [33554432]) f32.
// fp16 HMMA GEMM with branchless packed-u64 top-2; exact fp32 pair-check for
// mid-margin ties, full rescan only for tight bunches (margin < 0.06).

#define NPOS   32768
#define KEMB   1024
#define CDIM   256
#define QELEMS 8388608

#define THR_FULL 0.06f
#define THR_PAIR 0.12f

// ---------------------------------------------------------------------------
// device scratch
// ---------------------------------------------------------------------------
__device__ __align__(256) __half g_Xh[NPOS * CDIM];
__device__ __align__(256) __half g_Eh[KEMB * CDIM];
__device__ __align__(256) float  g_Et[KEMB * CDIM];   // fp32 codebook [k][c]
__device__ float g_esqh[KEMB];
__device__ int   g_idx[NPOS];
__device__ float g_loss;
__device__ int   g_nrepP;
__device__ int   g_repP[NPOS];
__device__ int   g_pk1[NPOS];
__device__ int   g_pk2[NPOS];
__device__ int   g_nrepF;
__device__ int   g_repF[NPOS];
__device__ unsigned long long g_best[NPOS];

// ---------------------------------------------------------------------------
// helpers
// ---------------------------------------------------------------------------
__device__ __forceinline__ uint32_t s2u(const void* p) {
    uint32_t a;
    asm("{ .reg .u64 t; cvta.to.shared.u64 t, %1; cvt.u32.u64 %0, t; }" : "=r"(a) : "l"(p));
    return a;
}
__device__ __forceinline__ void cp16(uint32_t s, const void* g) {
    asm volatile("cp.async.cg.shared.global [%0], [%1], 16;" :: "r"(s), "l"(g));
}
__device__ __forceinline__ void cpcommit() { asm volatile("cp.async.commit_group;"); }
template <int N>
__device__ __forceinline__ void cpwait() { asm volatile("cp.async.wait_group %0;" :: "n"(N)); }

__device__ __forceinline__ void ldm_x4(uint32_t& r0, uint32_t& r1, uint32_t& r2, uint32_t& r3,
                                       uint32_t addr) {
    asm volatile("ldmatrix.sync.aligned.m8n8.x4.shared.b16 {%0,%1,%2,%3}, [%4];"
                 : "=r"(r0), "=r"(r1), "=r"(r2), "=r"(r3) : "r"(addr));
}
__device__ __forceinline__ void mma16816(float* d, const uint32_t* a, const uint32_t* b) {
    asm volatile(
        "mma.sync.aligned.m16n8k16.row.col.f32.f16.f16.f32 "
        "{%0,%1,%2,%3}, {%4,%5,%6,%7}, {%8,%9}, {%0,%1,%2,%3};"
        : "+f"(d[0]), "+f"(d[1]), "+f"(d[2]), "+f"(d[3])
        : "r"(a[0]), "r"(a[1]), "r"(a[2]), "r"(a[3]), "r"(b[0]), "r"(b[1]));
}

typedef unsigned long long u64;

// orderable key: monotone u32 of float score, packed with codeword index.
__device__ __forceinline__ u64 pkey(float v, uint32_t k) {
    uint32_t u = __float_as_uint(v);
    u ^= (u & 0x80000000u) ? 0xFFFFFFFFu : 0x80000000u;
    return ((u64)u << 32) | k;
}
__device__ __forceinline__ float key_score(u64 key) {
    uint32_t u = (uint32_t)(key >> 32);
    u = (u & 0x80000000u) ? (u ^ 0x80000000u) : ~u;
    return __uint_as_float(u);
}
// insert candidate into sorted (key1 <= key2)
__device__ __forceinline__ void kins(u64& key1, u64& key2, u64 nk) {
    const u64 mx = max(key1, nk);
    key1 = min(key1, nk);
    key2 = min(key2, mx);
}
// merge another sorted pair
__device__ __forceinline__ void kmerge(u64& key1, u64& key2, u64 b1, u64 b2) {
    const u64 mx = max(key1, b1);
    key1 = min(key1, b1);
    key2 = min(min(key2, b2), mx);
}

// ---------------------------------------------------------------------------
// Kernel: embed prep — transpose, fp16+fp32 copies, 0.5||e||^2, counter reset
// ---------------------------------------------------------------------------
__global__ void k_prep_embed(const float* __restrict__ src) {
    __shared__ float Xs[32][257];
    const int t = threadIdx.x;
    const int hw0 = blockIdx.x * 32;
    const int lane = t & 31, w = t >> 5;

    #pragma unroll
    for (int i = 0; i < 32; ++i) {
        int c = w + i * 8;
        Xs[lane][c] = src[(size_t)c * 1024 + hw0 + lane];
    }
    __syncthreads();

    #pragma unroll
    for (int rr = 0; rr < 4; ++rr) {
        int r = w * 4 + rr;
        size_t ob = (size_t)(hw0 + r) * CDIM;
        #pragma unroll
        for (int j = 0; j < 8; ++j) {
            int c = lane + 32 * j;
            float x = Xs[r][c];
            g_Eh[ob + c] = __float2half_rn(x);
            g_Et[ob + c] = x;
        }
    }
    if (t < 32) {
        float s2 = 0.f;
        #pragma unroll 8
        for (int c = 0; c < CDIM; ++c) s2 = fmaf(Xs[t][c], Xs[t][c], s2);
        g_esqh[hw0 + t] = 0.5f * s2;
    }
    if (blockIdx.x == 0 && t == 0) { g_loss = 0.f; g_nrepP = 0; g_nrepF = 0; }
}

// ---------------------------------------------------------------------------
// Kernel: input prep — transpose + fp16 convert. Grid 1024 x 256.
// ---------------------------------------------------------------------------
__global__ void k_prep_x(const float* __restrict__ src) {
    __shared__ float Xs[32][257];
    const int t = threadIdx.x;
    const int s = blockIdx.x >> 5;
    const int hw0 = (blockIdx.x & 31) * 32;
    const int lane = t & 31, w = t >> 5;
    const float* sp = src + (size_t)s * (CDIM * 1024);

    #pragma unroll
    for (int i = 0; i < 32; ++i) {
        int c = w + i * 8;
        Xs[lane][c] = sp[(size_t)c * 1024 + hw0 + lane];
    }
    __syncthreads();

    #pragma unroll
    for (int rr = 0; rr < 4; ++rr) {
        int r = w * 4 + rr;
        size_t ob = ((size_t)s * 1024 + hw0 + r) * CDIM;
        #pragma unroll
        for (int j = 0; j < 8; ++j) {
            int c = lane + 32 * j;
            g_Xh[ob + c] = __float2half_rn(Xs[r][c]);
        }
    }
}

// ---------------------------------------------------------------------------
// Kernel: fp16 HMMA GEMM + packed-key top-2 argmin. Grid 256.
// ---------------------------------------------------------------------------
#define ROWB   80
#define STG_A  (128 * ROWB)
#define STG    (2 * STG_A)
#define NCHUNK 64
#define MMA_SMEM (3 * STG)

__global__ __launch_bounds__(256, 2) void k_mma() {
    extern __shared__ char dsm[];
    const uint32_t sb = s2u(dsm);
    __shared__ float sEsq[1024];
    __shared__ u64 sK1[4][128];
    __shared__ u64 sK2[4][128];

    const int tid = threadIdx.x;
    const int l   = tid & 31;
    const int wid = tid >> 5;
    const int wm  = wid & 1;
    const int wn  = wid >> 1;

    const int n0 = blockIdx.x * 128;

    for (int i = tid; i < 1024; i += 256) sEsq[i] = g_esqh[i];

    const __half* Ag0 = g_Xh + (size_t)n0 * CDIM;

    auto load_chunk = [&](int ci) {
        const int kb = ci >> 3, c = ci & 7;
        const __half* Ag = Ag0 + c * 32;
        const __half* Bg = g_Eh + (size_t)(kb * 128) * CDIM + c * 32;
        const uint32_t ab = sb + (ci % 3) * STG, bbs = ab + STG_A;
        #pragma unroll
        for (int u = 0; u < 2; ++u) {
            const int idx = tid + u * 256;
            const int row = idx >> 2, q = idx & 3;
            cp16(ab  + row * ROWB + q * 16, Ag + (size_t)row * CDIM + q * 8);
            cp16(bbs + row * ROWB + q * 16, Bg + (size_t)row * CDIM + q * 8);
        }
        cpcommit();
    };

    // running top-2 for row = tid (threads 0..127)
    u64 rK1 = 0xFFFFFFFFFFFFFFFFull, rK2 = 0xFFFFFFFFFFFFFFFFull;

    load_chunk(0);
    load_chunk(1);
    load_chunk(2);

    #pragma unroll 1
    for (int kb = 0; kb < 8; ++kb) {
        const int k0 = kb * 128;
        float acc[4][4][4];
        #pragma unroll
        for (int i = 0; i < 4; ++i)
            #pragma unroll
            for (int j = 0; j < 4; ++j)
                #pragma unroll
                for (int r = 0; r < 4; ++r) acc[i][j][r] = 0.f;

        #pragma unroll 1
        for (int c = 0; c < 8; ++c) {
            const int ci = kb * 8 + c;
            if (ci <= NCHUNK - 3)      cpwait<2>();
            else if (ci == NCHUNK - 2) cpwait<1>();
            else                       cpwait<0>();
            __syncthreads();

            const uint32_t ab = sb + (ci % 3) * STG, bbs = ab + STG_A;
            #pragma unroll
            for (int ks = 0; ks < 2; ++ks) {
                uint32_t afr[4][4], bfr[4][2];
                #pragma unroll
                for (int mt = 0; mt < 4; ++mt)
                    ldm_x4(afr[mt][0], afr[mt][1], afr[mt][2], afr[mt][3],
                           ab + (uint32_t)(wm * 64 + mt * 16 + (l & 15)) * ROWB
                              + (uint32_t)(ks * 16 + (l >> 4) * 8) * 2);
                #pragma unroll
                for (int ntp = 0; ntp < 2; ++ntp)
                    ldm_x4(bfr[2 * ntp][0], bfr[2 * ntp][1],
                           bfr[2 * ntp + 1][0], bfr[2 * ntp + 1][1],
                           bbs + (uint32_t)(wn * 32 + ntp * 16 + ((l >> 4) & 1) * 8 + (l & 7)) * ROWB
                               + (uint32_t)(ks * 16 + ((l >> 3) & 1) * 8) * 2);
                #pragma unroll
                for (int mt = 0; mt < 4; ++mt)
                    #pragma unroll
                    for (int nt = 0; nt < 4; ++nt)
                        mma16816(acc[mt][nt], afr[mt], bfr[nt]);
            }
            __syncthreads();
            if (ci + 3 < NCHUNK) load_chunk(ci + 3);
        }

        // ---- epilogue: branchless packed-key top-2 over this 128-col block ----
        #pragma unroll
        for (int mt = 0; mt < 4; ++mt) {
            #pragma unroll
            for (int rr = 0; rr < 2; ++rr) {
                const int rowCTA = wm * 64 + mt * 16 + (l >> 2) + rr * 8;
                u64 key1 = 0xFFFFFFFFFFFFFFFFull, key2 = 0xFFFFFFFFFFFFFFFFull;
                #pragma unroll
                for (int nt = 0; nt < 4; ++nt) {
                    #pragma unroll
                    for (int cc = 0; cc < 2; ++cc) {
                        const int col = wn * 32 + nt * 8 + (l & 3) * 2 + cc;
                        kins(key1, key2, pkey(sEsq[k0 + col] - acc[mt][nt][rr * 2 + cc],
                                              (uint32_t)(k0 + col)));
                    }
                }
                #pragma unroll
                for (int off = 1; off <= 2; off <<= 1) {
                    const u64 b1 = __shfl_xor_sync(0xffffffffu, key1, off);
                    const u64 b2 = __shfl_xor_sync(0xffffffffu, key2, off);
                    kmerge(key1, key2, b1, b2);
                }
                if ((l & 3) == 0) { sK1[wn][rowCTA] = key1; sK2[wn][rowCTA] = key2; }
            }
        }
        __syncthreads();
        if (tid < 128) {
            #pragma unroll
            for (int w = 0; w < 4; ++w) kmerge(rK1, rK2, sK1[w][tid], sK2[w][tid]);
        }
        __syncthreads();
    }

    if (tid < 128) {
        const int n = n0 + tid;
        const int k1 = (int)(rK1 & 0xFFFFFFFFull);
        const int k2 = (int)(rK2 & 0xFFFFFFFFull);
        const float m = key_score(rK2) - key_score(rK1);
        g_idx[n] = k1;
        if (m < THR_FULL) {                 // tight bunch: full exact rescan
            g_best[n] = 0xFFFFFFFFFFFFFFFFull;
            int s = atomicAdd(&g_nrepF, 1);
            g_repF[s] = n;
        } else if (m < THR_PAIR) {          // top-2 duel: exact pair check
            int s = atomicAdd(&g_nrepP, 1);
            g_repP[s] = n; g_pk1[s] = k1; g_pk2[s] = k2;
        }
    }
}

// ---------------------------------------------------------------------------
// Kernel: exact fp32 pair check — one warp per flagged position.
// ---------------------------------------------------------------------------
__global__ __launch_bounds__(256) void k_check(const float* __restrict__ inp) {
    const int lane = threadIdx.x & 31;
    const int nw = (gridDim.x * blockDim.x) >> 5;
    const int np = g_nrepP;
    for (int e = (blockIdx.x * blockDim.x + threadIdx.x) >> 5; e < np; e += nw) {
        const int n = g_repP[e], k1 = g_pk1[e], k2 = g_pk2[e];
        const float* xb = inp + (size_t)(n >> 10) * (CDIM * 1024) + (n & 1023);
        const float4* E1 = (const float4*)(g_Et + (size_t)k1 * CDIM + lane * 8);
        const float4* E2 = (const float4*)(g_Et + (size_t)k2 * CDIM + lane * 8);
        float e1[8], e2[8];
        *(float4*)&e1[0] = E1[0]; *(float4*)&e1[4] = E1[1];
        *(float4*)&e2[0] = E2[0]; *(float4*)&e2[4] = E2[1];
        float d1 = 0.f, d2 = 0.f;
        #pragma unroll
        for (int j = 0; j < 8; ++j) {
            const float xv = xb[(size_t)(lane * 8 + j) * 1024];
            d1 = fmaf(xv, e1[j], d1);
            d2 = fmaf(xv, e2[j], d2);
        }
        #pragma unroll
        for (int off = 16; off; off >>= 1) {
            d1 += __shfl_xor_sync(0xffffffffu, d1, off);
            d2 += __shfl_xor_sync(0xffffffffu, d2, off);
        }
        if (lane == 0) {
            const float s1 = g_esqh[k1] - d1;
            const float s2 = g_esqh[k2] - d2;
            g_idx[n] = (s2 < s1 || (s2 == s1 && k2 < k1)) ? k2 : k1;
        }
    }
}

// ---------------------------------------------------------------------------
// Kernel: full exact rescan for tightly-bunched positions (few hundred).
// ---------------------------------------------------------------------------
__global__ __launch_bounds__(256) void k_rescan(const float* __restrict__ inp) {
    __shared__ float xs[8][260];
    __shared__ int   sn[8];
    const int t = threadIdx.x;
    const int w = t >> 5, lane = t & 31;
    const int nrep = g_nrepF;
    const int nbatch = (nrep + 7) >> 3;

    for (int bi = blockIdx.x; bi < nbatch; bi += gridDim.x) {
        const int base = bi * 8;
        if (t < 8) sn[t] = g_repF[min(base + t, nrep - 1)];
        __syncthreads();
        for (int i = t; i < 2048; i += 256) {
            const int pp = i >> 8, c = i & 255;
            const int n = sn[pp];
            xs[pp][c] = inp[(size_t)(n >> 10) * (CDIM * 1024) + (size_t)c * 1024 + (n & 1023)];
        }
        __syncthreads();

        #pragma unroll 1
        for (int ch = 0; ch < 4; ++ch) {
            const int k = w * 128 + ch * 32 + lane;
            const float4* Ep = (const float4*)(g_Et + (size_t)k * CDIM);
            float acc[8];
            #pragma unroll
            for (int r = 0; r < 8; ++r) acc[r] = 0.f;
            #pragma unroll 8
            for (int c4 = 0; c4 < 64; ++c4) {
                const float4 e = Ep[c4];
                #pragma unroll
                for (int r = 0; r < 8; ++r) {
                    const float4 x4 = *(const float4*)&xs[r][c4 * 4];
                    acc[r] = fmaf(x4.x, e.x, acc[r]);
                    acc[r] = fmaf(x4.y, e.y, acc[r]);
                    acc[r] = fmaf(x4.z, e.z, acc[r]);
                    acc[r] = fmaf(x4.w, e.w, acc[r]);
                }
            }
            const float eh = g_esqh[k];
            #pragma unroll
            for (int r = 0; r < 8; ++r) {
                u64 key = pkey(eh - acc[r], (uint32_t)k);
                #pragma unroll
                for (int off = 16; off; off >>= 1) {
                    const u64 o = __shfl_xor_sync(0xffffffffu, key, off);
                    key = min(key, o);
                }
                if (lane == 0) atomicMin(&g_best[sn[r]], key);
            }
        }
        __syncthreads();
    }
}

// ---------------------------------------------------------------------------
// Kernel: unpack rescanned indices
// ---------------------------------------------------------------------------
__global__ void k_repfin() {
    const int nrep = g_nrepF;
    for (int i = blockIdx.x * 256 + threadIdx.x; i < nrep; i += gridDim.x * 256) {
        const int n = g_repF[i];
        g_idx[n] = (int)(g_best[n] & 0xFFFFFFFFull);
    }
}

// ---------------------------------------------------------------------------
// Kernel: quantize gather + loss (32 positions/block, smem-staged rows)
// ---------------------------------------------------------------------------
__global__ __launch_bounds__(256) void k_quant(const float* __restrict__ inp,
                                               float* __restrict__ outq) {
    __shared__ float eq[32][257];
    __shared__ int   sidx[32];
    const int t  = threadIdx.x;
    const int n0 = blockIdx.x * 32;
    const int b  = n0 >> 10;
    const int hw0 = n0 & 1023;

    if (t < 32) sidx[t] = g_idx[n0 + t];
    __syncthreads();
    #pragma unroll 1
    for (int j = 0; j < 32; ++j) {
        eq[j][t] = g_Et[(size_t)sidx[j] * CDIM + t];
    }
    __syncthreads();

    const int hw_l = t & 31;
    const int cg   = t >> 5;
    const size_t base = (size_t)b * (CDIM * 1024) + hw0 + hw_l;

    float ls = 0.f;
    #pragma unroll 4
    for (int cb = 0; cb < 32; ++cb) {
        const int c = cb * 8 + cg;
        const size_t a = base + (size_t)c * 1024;
        const float x = inp[a];
        const float e = eq[hw_l][c];
        outq[a] = e;
        const float d = e - x;
        ls = fmaf(d, d, ls);
    }

    __shared__ float red[256];
    red[t] = ls;
    __syncthreads();
    #pragma unroll
    for (int s = 128; s; s >>= 1) {
        if (t < s) red[t] += red[t + s];
        __syncthreads();
    }
    if (t == 0) atomicAdd(&g_loss, red[0]);
}

// ---------------------------------------------------------------------------
// Kernel: onehot + loss scalar
// ---------------------------------------------------------------------------
__global__ void k_onehot(float* __restrict__ d_out) {
    float* oh = d_out + (QELEMS + 1);
    const int t  = threadIdx.x;
    const int r0 = blockIdx.x * 8;
    #pragma unroll
    for (int rr = 0; rr < 8; ++rr) {
        const int n   = r0 + rr;
        const int idx = g_idx[n];
        const size_t base = (size_t)n * KEMB;
        #pragma unroll
        for (int p = 0; p < 4; ++p) {
            const int j = t + p * 256;
            oh[base + j] = (j == idx) ? 1.0f : 0.0f;
        }
    }
    if (blockIdx.x == 0 && t == 0) {
        d_out[QELEMS] = 1.25f * g_loss / (float)QELEMS;
    }
}

// ---------------------------------------------------------------------------
extern "C" void kernel_launch(void* const* d_in, const int* in_sizes, int n_in,
                              void* d_out, int out_size) {
    const float* inp = (const float*)d_in[0];
    const float* emb = (const float*)d_in[1];
    float* out = (float*)d_out;

    cudaFuncSetAttribute(k_mma, cudaFuncAttributeMaxDynamicSharedMemorySize, MMA_SMEM);

    k_prep_embed<<<32, 256>>>(emb);
    k_prep_x<<<1024, 256>>>(inp);
    k_mma<<<256, 256, MMA_SMEM>>>();
    k_check<<<128, 256>>>(inp);
    k_rescan<<<48, 256>>>(inp);
    k_repfin<<<4, 256>>>();
    k_quant<<<1024, 256>>>(inp, out);
    k_onehot<<<4096, 256>>>(out);
}

// round 14
// speedup vs baseline: 1.0862x; 1.0862x over previous
#include <cuda_runtime.h>
#include <cuda_fp16.h>
#include <cstdint>

// VQ argmin: 32768 positions x 1024 codewords, C=256.
// inputs [32,256,32,32] f32, embed [256,1024] f32.
// out = concat(quantize_st [8388608], loss [1], onehot [33554432]) f32.
// fp16 HMMA GEMM (R10 epilogue + k2 tracking); tiered exact repair:
// margin>=0.12 done, 0.06..0.12 pair-check, <0.06 full rescan.

#define NPOS   32768
#define KEMB   1024
#define CDIM   256
#define QELEMS 8388608

#define THR_FULL 0.06f
#define THR_PAIR 0.12f

// ---------------------------------------------------------------------------
// device scratch
// ---------------------------------------------------------------------------
__device__ __align__(256) __half g_Xh[NPOS * CDIM];
__device__ __align__(256) __half g_Eh[KEMB * CDIM];
__device__ __align__(256) float  g_Et[KEMB * CDIM];   // fp32 codebook [k][c]
__device__ float g_esqh[KEMB];
__device__ int   g_idx[NPOS];
__device__ float g_loss;
__device__ int   g_nrepP;
__device__ int   g_repP[NPOS];
__device__ int   g_pk1[NPOS];
__device__ int   g_pk2[NPOS];
__device__ int   g_nrepF;
__device__ int   g_repF[NPOS];
__device__ unsigned long long g_best[NPOS];

typedef unsigned long long u64;

// ---------------------------------------------------------------------------
// helpers
// ---------------------------------------------------------------------------
__device__ __forceinline__ uint32_t s2u(const void* p) {
    uint32_t a;
    asm("{ .reg .u64 t; cvta.to.shared.u64 t, %1; cvt.u32.u64 %0, t; }" : "=r"(a) : "l"(p));
    return a;
}
__device__ __forceinline__ void cp16(uint32_t s, const void* g) {
    asm volatile("cp.async.cg.shared.global [%0], [%1], 16;" :: "r"(s), "l"(g));
}
__device__ __forceinline__ void cpcommit() { asm volatile("cp.async.commit_group;"); }
template <int N>
__device__ __forceinline__ void cpwait() { asm volatile("cp.async.wait_group %0;" :: "n"(N)); }

__device__ __forceinline__ void ldm_x4(uint32_t& r0, uint32_t& r1, uint32_t& r2, uint32_t& r3,
                                       uint32_t addr) {
    asm volatile("ldmatrix.sync.aligned.m8n8.x4.shared.b16 {%0,%1,%2,%3}, [%4];"
                 : "=r"(r0), "=r"(r1), "=r"(r2), "=r"(r3) : "r"(addr));
}
__device__ __forceinline__ void mma16816(float* d, const uint32_t* a, const uint32_t* b) {
    asm volatile(
        "mma.sync.aligned.m16n8k16.row.col.f32.f16.f16.f32 "
        "{%0,%1,%2,%3}, {%4,%5,%6,%7}, {%8,%9}, {%0,%1,%2,%3};"
        : "+f"(d[0]), "+f"(d[1]), "+f"(d[2]), "+f"(d[3])
        : "r"(a[0]), "r"(a[1]), "r"(a[2]), "r"(a[3]), "r"(b[0]), "r"(b[1]));
}

__device__ __forceinline__ u64 pkey(float v, uint32_t k) {
    uint32_t u = __float_as_uint(v);
    u ^= (u & 0x80000000u) ? 0xFFFFFFFFu : 0x80000000u;
    return ((u64)u << 32) | k;
}

// ---------------------------------------------------------------------------
// Kernel: embed prep — transpose, fp16+fp32 copies, 0.5||e||^2, counter reset
// ---------------------------------------------------------------------------
__global__ void k_prep_embed(const float* __restrict__ src) {
    __shared__ float Xs[32][257];
    const int t = threadIdx.x;
    const int hw0 = blockIdx.x * 32;
    const int lane = t & 31, w = t >> 5;

    #pragma unroll
    for (int i = 0; i < 32; ++i) {
        int c = w + i * 8;
        Xs[lane][c] = src[(size_t)c * 1024 + hw0 + lane];
    }
    __syncthreads();

    #pragma unroll
    for (int rr = 0; rr < 4; ++rr) {
        int r = w * 4 + rr;
        size_t ob = (size_t)(hw0 + r) * CDIM;
        #pragma unroll
        for (int j = 0; j < 8; ++j) {
            int c = lane + 32 * j;
            float x = Xs[r][c];
            g_Eh[ob + c] = __float2half_rn(x);
            g_Et[ob + c] = x;
        }
    }
    if (t < 32) {
        float s2 = 0.f;
        #pragma unroll 8
        for (int c = 0; c < CDIM; ++c) s2 = fmaf(Xs[t][c], Xs[t][c], s2);
        g_esqh[hw0 + t] = 0.5f * s2;
    }
    if (blockIdx.x == 0 && t == 0) { g_loss = 0.f; g_nrepP = 0; g_nrepF = 0; }
}

// ---------------------------------------------------------------------------
// Kernel: input prep — transpose + fp16 convert. Grid 1024 x 256.
// ---------------------------------------------------------------------------
__global__ void k_prep_x(const float* __restrict__ src) {
    __shared__ float Xs[32][257];
    const int t = threadIdx.x;
    const int s = blockIdx.x >> 5;
    const int hw0 = (blockIdx.x & 31) * 32;
    const int lane = t & 31, w = t >> 5;
    const float* sp = src + (size_t)s * (CDIM * 1024);

    #pragma unroll
    for (int i = 0; i < 32; ++i) {
        int c = w + i * 8;
        Xs[lane][c] = sp[(size_t)c * 1024 + hw0 + lane];
    }
    __syncthreads();

    #pragma unroll
    for (int rr = 0; rr < 4; ++rr) {
        int r = w * 4 + rr;
        size_t ob = ((size_t)s * 1024 + hw0 + r) * CDIM;
        #pragma unroll
        for (int j = 0; j < 8; ++j) {
            int c = lane + 32 * j;
            g_Xh[ob + c] = __float2half_rn(Xs[r][c]);
        }
    }
}

// ---------------------------------------------------------------------------
// Kernel: fp16 HMMA GEMM + top-2 argmin (R10 float-compare epilogue + k2).
// Grid 256: one CTA per 128 positions, 64 chunks of BK=32, 3-stage pipeline.
// ---------------------------------------------------------------------------
#define ROWB   80
#define STG_A  (128 * ROWB)
#define STG    (2 * STG_A)
#define NCHUNK 64
#define MMA_SMEM (3 * STG)

__global__ __launch_bounds__(256, 2) void k_mma() {
    extern __shared__ char dsm[];
    const uint32_t sb = s2u(dsm);
    __shared__ float sEsq[1024];
    __shared__ float sv1[4][128], sv2[4][128];
    __shared__ int   sk1[4][128], sk2[4][128];

    const int tid = threadIdx.x;
    const int l   = tid & 31;
    const int wid = tid >> 5;
    const int wm  = wid & 1;
    const int wn  = wid >> 1;

    const int n0 = blockIdx.x * 128;

    for (int i = tid; i < 1024; i += 256) sEsq[i] = g_esqh[i];

    const __half* Ag0 = g_Xh + (size_t)n0 * CDIM;

    auto load_chunk = [&](int ci) {
        const int kb = ci >> 3, c = ci & 7;
        const __half* Ag = Ag0 + c * 32;
        const __half* Bg = g_Eh + (size_t)(kb * 128) * CDIM + c * 32;
        const uint32_t ab = sb + (ci % 3) * STG, bbs = ab + STG_A;
        #pragma unroll
        for (int u = 0; u < 2; ++u) {
            const int idx = tid + u * 256;
            const int row = idx >> 2, q = idx & 3;
            cp16(ab  + row * ROWB + q * 16, Ag + (size_t)row * CDIM + q * 8);
            cp16(bbs + row * ROWB + q * 16, Bg + (size_t)row * CDIM + q * 8);
        }
        cpcommit();
    };

    // running top-2 (with indices) for row = tid (threads 0..127)
    float rv1 = 3.4e38f, rv2 = 3.4e38f;
    int   rk1 = 0, rk2 = 0;

    load_chunk(0);
    load_chunk(1);
    load_chunk(2);

    #pragma unroll 1
    for (int kb = 0; kb < 8; ++kb) {
        const int k0 = kb * 128;
        float acc[4][4][4];
        #pragma unroll
        for (int i = 0; i < 4; ++i)
            #pragma unroll
            for (int j = 0; j < 4; ++j)
                #pragma unroll
                for (int r = 0; r < 4; ++r) acc[i][j][r] = 0.f;

        #pragma unroll 1
        for (int c = 0; c < 8; ++c) {
            const int ci = kb * 8 + c;
            if (ci <= NCHUNK - 3)      cpwait<2>();
            else if (ci == NCHUNK - 2) cpwait<1>();
            else                       cpwait<0>();
            __syncthreads();

            const uint32_t ab = sb + (ci % 3) * STG, bbs = ab + STG_A;
            #pragma unroll
            for (int ks = 0; ks < 2; ++ks) {
                uint32_t afr[4][4], bfr[4][2];
                #pragma unroll
                for (int mt = 0; mt < 4; ++mt)
                    ldm_x4(afr[mt][0], afr[mt][1], afr[mt][2], afr[mt][3],
                           ab + (uint32_t)(wm * 64 + mt * 16 + (l & 15)) * ROWB
                              + (uint32_t)(ks * 16 + (l >> 4) * 8) * 2);
                #pragma unroll
                for (int ntp = 0; ntp < 2; ++ntp)
                    ldm_x4(bfr[2 * ntp][0], bfr[2 * ntp][1],
                           bfr[2 * ntp + 1][0], bfr[2 * ntp + 1][1],
                           bbs + (uint32_t)(wn * 32 + ntp * 16 + ((l >> 4) & 1) * 8 + (l & 7)) * ROWB
                               + (uint32_t)(ks * 16 + ((l >> 3) & 1) * 8) * 2);
                #pragma unroll
                for (int mt = 0; mt < 4; ++mt)
                    #pragma unroll
                    for (int nt = 0; nt < 4; ++nt)
                        mma16816(acc[mt][nt], afr[mt], bfr[nt]);
            }
            __syncthreads();
            if (ci + 3 < NCHUNK) load_chunk(ci + 3);
        }

        // ---- epilogue: per-row top-2 (values + indices), float compares ----
        #pragma unroll
        for (int mt = 0; mt < 4; ++mt) {
            #pragma unroll
            for (int rr = 0; rr < 2; ++rr) {
                const int rowCTA = wm * 64 + mt * 16 + (l >> 2) + rr * 8;
                float v1 = 3.4e38f, v2 = 3.4e38f;
                int   k1 = 0, k2 = 0;
                #pragma unroll
                for (int nt = 0; nt < 4; ++nt) {
                    #pragma unroll
                    for (int cc = 0; cc < 2; ++cc) {
                        const int col = wn * 32 + nt * 8 + (l & 3) * 2 + cc;
                        const float v = sEsq[k0 + col] - acc[mt][nt][rr * 2 + cc];
                        if (v < v1)      { v2 = v1; k2 = k1; v1 = v; k1 = k0 + col; }
                        else if (v < v2) { v2 = v; k2 = k0 + col; }
                    }
                }
                #pragma unroll
                for (int off = 1; off <= 2; off <<= 1) {
                    const float ov1 = __shfl_xor_sync(0xffffffffu, v1, off);
                    const float ov2 = __shfl_xor_sync(0xffffffffu, v2, off);
                    const int   ok1 = __shfl_xor_sync(0xffffffffu, k1, off);
                    const int   ok2 = __shfl_xor_sync(0xffffffffu, k2, off);
                    if (ov1 < v1 || (ov1 == v1 && ok1 < k1)) {
                        if (v1 < ov2) { v2 = v1; k2 = k1; }
                        else          { v2 = ov2; k2 = ok2; }
                        v1 = ov1; k1 = ok1;
                    } else {
                        if (ov1 < v2) { v2 = ov1; k2 = ok1; }
                    }
                }
                if ((l & 3) == 0) {
                    sv1[wn][rowCTA] = v1; sv2[wn][rowCTA] = v2;
                    sk1[wn][rowCTA] = k1; sk2[wn][rowCTA] = k2;
                }
            }
        }
        __syncthreads();
        if (tid < 128) {
            #pragma unroll
            for (int w = 0; w < 4; ++w) {
                const float pv1 = sv1[w][tid], pv2 = sv2[w][tid];
                const int   pk1 = sk1[w][tid], pk2 = sk2[w][tid];
                if (pv1 < rv1 || (pv1 == rv1 && pk1 < rk1)) {
                    if (rv1 < pv2) { rv2 = rv1; rk2 = rk1; }
                    else           { rv2 = pv2; rk2 = pk2; }
                    rv1 = pv1; rk1 = pk1;
                } else {
                    if (pv1 < rv2) { rv2 = pv1; rk2 = pk1; }
                }
            }
        }
        __syncthreads();
    }

    if (tid < 128) {
        const int n = n0 + tid;
        const float m = rv2 - rv1;
        g_idx[n] = rk1;
        if (m < THR_FULL) {                 // tight bunch: full exact rescan
            g_best[n] = 0xFFFFFFFFFFFFFFFFull;
            int s = atomicAdd(&g_nrepF, 1);
            g_repF[s] = n;
        } else if (m < THR_PAIR) {          // top-2 duel: exact pair check
            int s = atomicAdd(&g_nrepP, 1);
            g_repP[s] = n; g_pk1[s] = rk1; g_pk2[s] = rk2;
        }
    }
}

// ---------------------------------------------------------------------------
// Kernel: exact fp32 pair check — one warp per flagged position.
// ---------------------------------------------------------------------------
__global__ __launch_bounds__(256) void k_check(const float* __restrict__ inp) {
    const int lane = threadIdx.x & 31;
    const int nw = (gridDim.x * blockDim.x) >> 5;
    const int np = g_nrepP;
    for (int e = (blockIdx.x * blockDim.x + threadIdx.x) >> 5; e < np; e += nw) {
        const int n = g_repP[e], k1 = g_pk1[e], k2 = g_pk2[e];
        const float* xb = inp + (size_t)(n >> 10) * (CDIM * 1024) + (n & 1023);
        const float4* E1 = (const float4*)(g_Et + (size_t)k1 * CDIM + lane * 8);
        const float4* E2 = (const float4*)(g_Et + (size_t)k2 * CDIM + lane * 8);
        float e1[8], e2[8];
        *(float4*)&e1[0] = E1[0]; *(float4*)&e1[4] = E1[1];
        *(float4*)&e2[0] = E2[0]; *(float4*)&e2[4] = E2[1];
        float d1 = 0.f, d2 = 0.f;
        #pragma unroll
        for (int j = 0; j < 8; ++j) {
            const float xv = xb[(size_t)(lane * 8 + j) * 1024];
            d1 = fmaf(xv, e1[j], d1);
            d2 = fmaf(xv, e2[j], d2);
        }
        #pragma unroll
        for (int off = 16; off; off >>= 1) {
            d1 += __shfl_xor_sync(0xffffffffu, d1, off);
            d2 += __shfl_xor_sync(0xffffffffu, d2, off);
        }
        if (lane == 0) {
            const float s1 = g_esqh[k1] - d1;
            const float s2 = g_esqh[k2] - d2;
            g_idx[n] = (s2 < s1 || (s2 == s1 && k2 < k1)) ? k2 : k1;
        }
    }
}

// ---------------------------------------------------------------------------
// Kernel: full exact rescan for tightly-bunched positions (few hundred).
// ---------------------------------------------------------------------------
__global__ __launch_bounds__(256) void k_rescan(const float* __restrict__ inp) {
    __shared__ float xs[8][260];
    __shared__ int   sn[8];
    const int t = threadIdx.x;
    const int w = t >> 5, lane = t & 31;
    const int nrep = g_nrepF;
    const int nbatch = (nrep + 7) >> 3;

    for (int bi = blockIdx.x; bi < nbatch; bi += gridDim.x) {
        const int base = bi * 8;
        if (t < 8) sn[t] = g_repF[min(base + t, nrep - 1)];
        __syncthreads();
        for (int i = t; i < 2048; i += 256) {
            const int pp = i >> 8, c = i & 255;
            const int n = sn[pp];
            xs[pp][c] = inp[(size_t)(n >> 10) * (CDIM * 1024) + (size_t)c * 1024 + (n & 1023)];
        }
        __syncthreads();

        #pragma unroll 1
        for (int ch = 0; ch < 4; ++ch) {
            const int k = w * 128 + ch * 32 + lane;
            const float4* Ep = (const float4*)(g_Et + (size_t)k * CDIM);
            float acc[8];
            #pragma unroll
            for (int r = 0; r < 8; ++r) acc[r] = 0.f;
            #pragma unroll 8
            for (int c4 = 0; c4 < 64; ++c4) {
                const float4 e = Ep[c4];
                #pragma unroll
                for (int r = 0; r < 8; ++r) {
                    const float4 x4 = *(const float4*)&xs[r][c4 * 4];
                    acc[r] = fmaf(x4.x, e.x, acc[r]);
                    acc[r] = fmaf(x4.y, e.y, acc[r]);
                    acc[r] = fmaf(x4.z, e.z, acc[r]);
                    acc[r] = fmaf(x4.w, e.w, acc[r]);
                }
            }
            const float eh = g_esqh[k];
            #pragma unroll
            for (int r = 0; r < 8; ++r) {
                u64 key = pkey(eh - acc[r], (uint32_t)k);
                #pragma unroll
                for (int off = 16; off; off >>= 1) {
                    const u64 o = __shfl_xor_sync(0xffffffffu, key, off);
                    key = min(key, o);
                }
                if (lane == 0) atomicMin(&g_best[sn[r]], key);
            }
        }
        __syncthreads();
    }
}

// ---------------------------------------------------------------------------
// Kernel: unpack rescanned indices
// ---------------------------------------------------------------------------
__global__ void k_repfin() {
    const int nrep = g_nrepF;
    for (int i = blockIdx.x * 256 + threadIdx.x; i < nrep; i += gridDim.x * 256) {
        const int n = g_repF[i];
        g_idx[n] = (int)(g_best[n] & 0xFFFFFFFFull);
    }
}

// ---------------------------------------------------------------------------
// Kernel: quantize gather + loss (32 positions/block, smem-staged rows)
// ---------------------------------------------------------------------------
__global__ __launch_bounds__(256) void k_quant(const float* __restrict__ inp,
                                               float* __restrict__ outq) {
    __shared__ float eq[32][257];
    __shared__ int   sidx[32];
    const int t  = threadIdx.x;
    const int n0 = blockIdx.x * 32;
    const int b  = n0 >> 10;
    const int hw0 = n0 & 1023;

    if (t < 32) sidx[t] = g_idx[n0 + t];
    __syncthreads();
    #pragma unroll 1
    for (int j = 0; j < 32; ++j) {
        eq[j][t] = g_Et[(size_t)sidx[j] * CDIM + t];
    }
    __syncthreads();

    const int hw_l = t & 31;
    const int cg   = t >> 5;
    const size_t base = (size_t)b * (CDIM * 1024) + hw0 + hw_l;

    float ls = 0.f;
    #pragma unroll 4
    for (int cb = 0; cb < 32; ++cb) {
        const int c = cb * 8 + cg;
        const size_t a = base + (size_t)c * 1024;
        const float x = inp[a];
        const float e = eq[hw_l][c];
        outq[a] = e;
        const float d = e - x;
        ls = fmaf(d, d, ls);
    }

    __shared__ float red[256];
    red[t] = ls;
    __syncthreads();
    #pragma unroll
    for (int s = 128; s; s >>= 1) {
        if (t < s) red[t] += red[t + s];
        __syncthreads();
    }
    if (t == 0) atomicAdd(&g_loss, red[0]);
}

// ---------------------------------------------------------------------------
// Kernel: onehot + loss scalar
// ---------------------------------------------------------------------------
__global__ void k_onehot(float* __restrict__ d_out) {
    float* oh = d_out + (QELEMS + 1);
    const int t  = threadIdx.x;
    const int r0 = blockIdx.x * 8;
    #pragma unroll
    for (int rr = 0; rr < 8; ++rr) {
        const int n   = r0 + rr;
        const int idx = g_idx[n];
        const size_t base = (size_t)n * KEMB;
        #pragma unroll
        for (int p = 0; p < 4; ++p) {
            const int j = t + p * 256;
            oh[base + j] = (j == idx) ? 1.0f : 0.0f;
        }
    }
    if (blockIdx.x == 0 && t == 0) {
        d_out[QELEMS] = 1.25f * g_loss / (float)QELEMS;
    }
}

// ---------------------------------------------------------------------------
extern "C" void kernel_launch(void* const* d_in, const int* in_sizes, int n_in,
                              void* d_out, int out_size) {
    const float* inp = (const float*)d_in[0];
    const float* emb = (const float*)d_in[1];
    float* out = (float*)d_out;

    cudaFuncSetAttribute(k_mma, cudaFuncAttributeMaxDynamicSharedMemorySize, MMA_SMEM);

    k_prep_embed<<<32, 256>>>(emb);
    k_prep_x<<<1024, 256>>>(inp);
    k_mma<<<256, 256, MMA_SMEM>>>();
    k_check<<<128, 256>>>(inp);
    k_rescan<<<48, 256>>>(inp);
    k_repfin<<<4, 256>>>();
    k_quant<<<1024, 256>>>(inp, out);
    k_onehot<<<4096, 256>>>(out);
}

// round 16
// speedup vs baseline: 1.4339x; 1.3201x over previous
#include <cuda_runtime.h>
#include <cuda_fp16.h>
#include <cstdint>

// VQ argmin: 32768 positions x 1024 codewords, C=256.
// inputs [32,256,32,32] f32, embed [256,1024] f32.
// out = concat(quantize_st [8388608], loss [1], onehot [33554432]) f32.
// fp16 HMMA GEMM (R10 epilogue, top-2 values + top-1 index only);
// all near-ties (margin < 0.12) -> flat exact fp32 full rescan.

#define NPOS   32768
#define KEMB   1024
#define CDIM   256
#define QELEMS 8388608

#define REP_THR 0.12f

// ---------------------------------------------------------------------------
// device scratch
// ---------------------------------------------------------------------------
__device__ __align__(256) __half g_Xh[NPOS * CDIM];
__device__ __align__(256) __half g_Eh[KEMB * CDIM];
__device__ __align__(256) float  g_Et[KEMB * CDIM];   // fp32 codebook [k][c]
__device__ float g_esqh[KEMB];
__device__ int   g_idx[NPOS];
__device__ float g_loss;
__device__ int   g_nrep;
__device__ int   g_rep[NPOS];
__device__ unsigned long long g_best[NPOS];

typedef unsigned long long u64;

// ---------------------------------------------------------------------------
// helpers
// ---------------------------------------------------------------------------
__device__ __forceinline__ uint32_t s2u(const void* p) {
    uint32_t a;
    asm("{ .reg .u64 t; cvta.to.shared.u64 t, %1; cvt.u32.u64 %0, t; }" : "=r"(a) : "l"(p));
    return a;
}
__device__ __forceinline__ void cp16(uint32_t s, const void* g) {
    asm volatile("cp.async.cg.shared.global [%0], [%1], 16;" :: "r"(s), "l"(g));
}
__device__ __forceinline__ void cpcommit() { asm volatile("cp.async.commit_group;"); }
template <int N>
__device__ __forceinline__ void cpwait() { asm volatile("cp.async.wait_group %0;" :: "n"(N)); }

__device__ __forceinline__ void ldm_x4(uint32_t& r0, uint32_t& r1, uint32_t& r2, uint32_t& r3,
                                       uint32_t addr) {
    asm volatile("ldmatrix.sync.aligned.m8n8.x4.shared.b16 {%0,%1,%2,%3}, [%4];"
                 : "=r"(r0), "=r"(r1), "=r"(r2), "=r"(r3) : "r"(addr));
}
__device__ __forceinline__ void mma16816(float* d, const uint32_t* a, const uint32_t* b) {
    asm volatile(
        "mma.sync.aligned.m16n8k16.row.col.f32.f16.f16.f32 "
        "{%0,%1,%2,%3}, {%4,%5,%6,%7}, {%8,%9}, {%0,%1,%2,%3};"
        : "+f"(d[0]), "+f"(d[1]), "+f"(d[2]), "+f"(d[3])
        : "r"(a[0]), "r"(a[1]), "r"(a[2]), "r"(a[3]), "r"(b[0]), "r"(b[1]));
}

__device__ __forceinline__ u64 pkey(float v, uint32_t k) {
    uint32_t u = __float_as_uint(v);
    u ^= (u & 0x80000000u) ? 0xFFFFFFFFu : 0x80000000u;
    return ((u64)u << 32) | k;
}

// ---------------------------------------------------------------------------
// Kernel: embed prep — transpose, fp16+fp32 copies, 0.5||e||^2, counter reset
// ---------------------------------------------------------------------------
__global__ void k_prep_embed(const float* __restrict__ src) {
    __shared__ float Xs[32][257];
    const int t = threadIdx.x;
    const int hw0 = blockIdx.x * 32;
    const int lane = t & 31, w = t >> 5;

    #pragma unroll
    for (int i = 0; i < 32; ++i) {
        int c = w + i * 8;
        Xs[lane][c] = src[(size_t)c * 1024 + hw0 + lane];
    }
    __syncthreads();

    #pragma unroll
    for (int rr = 0; rr < 4; ++rr) {
        int r = w * 4 + rr;
        size_t ob = (size_t)(hw0 + r) * CDIM;
        #pragma unroll
        for (int j = 0; j < 8; ++j) {
            int c = lane + 32 * j;
            float x = Xs[r][c];
            g_Eh[ob + c] = __float2half_rn(x);
            g_Et[ob + c] = x;
        }
    }
    if (t < 32) {
        float s2 = 0.f;
        #pragma unroll 8
        for (int c = 0; c < CDIM; ++c) s2 = fmaf(Xs[t][c], Xs[t][c], s2);
        g_esqh[hw0 + t] = 0.5f * s2;
    }
    if (blockIdx.x == 0 && t == 0) { g_loss = 0.f; g_nrep = 0; }
}

// ---------------------------------------------------------------------------
// Kernel: input prep — transpose + fp16 convert. Grid 1024 x 256.
// ---------------------------------------------------------------------------
__global__ void k_prep_x(const float* __restrict__ src) {
    __shared__ float Xs[32][257];
    const int t = threadIdx.x;
    const int s = blockIdx.x >> 5;
    const int hw0 = (blockIdx.x & 31) * 32;
    const int lane = t & 31, w = t >> 5;
    const float* sp = src + (size_t)s * (CDIM * 1024);

    #pragma unroll
    for (int i = 0; i < 32; ++i) {
        int c = w + i * 8;
        Xs[lane][c] = sp[(size_t)c * 1024 + hw0 + lane];
    }
    __syncthreads();

    #pragma unroll
    for (int rr = 0; rr < 4; ++rr) {
        int r = w * 4 + rr;
        size_t ob = ((size_t)s * 1024 + hw0 + r) * CDIM;
        #pragma unroll
        for (int j = 0; j < 8; ++j) {
            int c = lane + 32 * j;
            g_Xh[ob + c] = __float2half_rn(Xs[r][c]);
        }
    }
}

// ---------------------------------------------------------------------------
// Kernel: fp16 HMMA GEMM + top-2 argmin — R10 configuration, unmodified
// except the flag threshold. Grid 256: one CTA per 128 positions.
// ---------------------------------------------------------------------------
#define ROWB   80
#define STG_A  (128 * ROWB)
#define STG    (2 * STG_A)
#define NCHUNK 64
#define MMA_SMEM (3 * STG)

__global__ __launch_bounds__(256, 2) void k_mma() {
    extern __shared__ char dsm[];
    const uint32_t sb = s2u(dsm);
    __shared__ float sEsq[1024];
    __shared__ float sv1[4][128];
    __shared__ float sv2[4][128];
    __shared__ int   sk1[4][128];

    const int tid = threadIdx.x;
    const int l   = tid & 31;
    const int wid = tid >> 5;
    const int wm  = wid & 1;
    const int wn  = wid >> 1;

    const int n0 = blockIdx.x * 128;

    for (int i = tid; i < 1024; i += 256) sEsq[i] = g_esqh[i];

    const __half* Ag0 = g_Xh + (size_t)n0 * CDIM;

    auto load_chunk = [&](int ci) {
        const int kb = ci >> 3, c = ci & 7;
        const __half* Ag = Ag0 + c * 32;
        const __half* Bg = g_Eh + (size_t)(kb * 128) * CDIM + c * 32;
        const uint32_t ab = sb + (ci % 3) * STG, bbs = ab + STG_A;
        #pragma unroll
        for (int u = 0; u < 2; ++u) {
            const int idx = tid + u * 256;
            const int row = idx >> 2, q = idx & 3;
            cp16(ab  + row * ROWB + q * 16, Ag + (size_t)row * CDIM + q * 8);
            cp16(bbs + row * ROWB + q * 16, Bg + (size_t)row * CDIM + q * 8);
        }
        cpcommit();
    };

    float rv1 = 3.4e38f, rv2 = 3.4e38f;
    int   rk1 = 0;

    load_chunk(0);
    load_chunk(1);
    load_chunk(2);

    #pragma unroll 1
    for (int kb = 0; kb < 8; ++kb) {
        const int k0 = kb * 128;
        float acc[4][4][4];
        #pragma unroll
        for (int i = 0; i < 4; ++i)
            #pragma unroll
            for (int j = 0; j < 4; ++j)
                #pragma unroll
                for (int r = 0; r < 4; ++r) acc[i][j][r] = 0.f;

        #pragma unroll 1
        for (int c = 0; c < 8; ++c) {
            const int ci = kb * 8 + c;
            if (ci <= NCHUNK - 3)      cpwait<2>();
            else if (ci == NCHUNK - 2) cpwait<1>();
            else                       cpwait<0>();
            __syncthreads();

            const uint32_t ab = sb + (ci % 3) * STG, bbs = ab + STG_A;
            #pragma unroll
            for (int ks = 0; ks < 2; ++ks) {
                uint32_t afr[4][4], bfr[4][2];
                #pragma unroll
                for (int mt = 0; mt < 4; ++mt)
                    ldm_x4(afr[mt][0], afr[mt][1], afr[mt][2], afr[mt][3],
                           ab + (uint32_t)(wm * 64 + mt * 16 + (l & 15)) * ROWB
                              + (uint32_t)(ks * 16 + (l >> 4) * 8) * 2);
                #pragma unroll
                for (int ntp = 0; ntp < 2; ++ntp)
                    ldm_x4(bfr[2 * ntp][0], bfr[2 * ntp][1],
                           bfr[2 * ntp + 1][0], bfr[2 * ntp + 1][1],
                           bbs + (uint32_t)(wn * 32 + ntp * 16 + ((l >> 4) & 1) * 8 + (l & 7)) * ROWB
                               + (uint32_t)(ks * 16 + ((l >> 3) & 1) * 8) * 2);
                #pragma unroll
                for (int mt = 0; mt < 4; ++mt)
                    #pragma unroll
                    for (int nt = 0; nt < 4; ++nt)
                        mma16816(acc[mt][nt], afr[mt], bfr[nt]);
            }
            __syncthreads();
            if (ci + 3 < NCHUNK) load_chunk(ci + 3);
        }

        // ---- epilogue: per-row top-2 (R10 form: v1,k1,v2) ----
        #pragma unroll
        for (int mt = 0; mt < 4; ++mt) {
            #pragma unroll
            for (int rr = 0; rr < 2; ++rr) {
                const int rowCTA = wm * 64 + mt * 16 + (l >> 2) + rr * 8;
                float v1 = 3.4e38f, v2 = 3.4e38f;
                int   k1 = 0;
                #pragma unroll
                for (int nt = 0; nt < 4; ++nt) {
                    #pragma unroll
                    for (int cc = 0; cc < 2; ++cc) {
                        const int col = wn * 32 + nt * 8 + (l & 3) * 2 + cc;
                        const float v = sEsq[k0 + col] - acc[mt][nt][rr * 2 + cc];
                        if (v < v1)      { v2 = v1; v1 = v; k1 = k0 + col; }
                        else if (v < v2) { v2 = v; }
                    }
                }
                #pragma unroll
                for (int off = 1; off <= 2; off <<= 1) {
                    const float ov1 = __shfl_xor_sync(0xffffffffu, v1, off);
                    const float ov2 = __shfl_xor_sync(0xffffffffu, v2, off);
                    const int   ok1 = __shfl_xor_sync(0xffffffffu, k1, off);
                    if (ov1 < v1 || (ov1 == v1 && ok1 < k1)) {
                        v2 = fminf(v1, ov2); v1 = ov1; k1 = ok1;
                    } else {
                        v2 = fminf(v2, ov1);
                    }
                }
                if ((l & 3) == 0) {
                    sv1[wn][rowCTA] = v1; sv2[wn][rowCTA] = v2; sk1[wn][rowCTA] = k1;
                }
            }
        }
        __syncthreads();
        if (tid < 128) {
            #pragma unroll
            for (int w = 0; w < 4; ++w) {
                const float pv1 = sv1[w][tid], pv2 = sv2[w][tid];
                const int   pk  = sk1[w][tid];
                if (pv1 < rv1 || (pv1 == rv1 && pk < rk1)) {
                    rv2 = fminf(rv1, pv2); rv1 = pv1; rk1 = pk;
                } else {
                    rv2 = fminf(rv2, pv1);
                }
            }
        }
        __syncthreads();
    }

    if (tid < 128) {
        const int n = n0 + tid;
        g_idx[n] = rk1;
        if (rv2 - rv1 < REP_THR) {         // near-tie: exact full rescan
            g_best[n] = 0xFFFFFFFFFFFFFFFFull;
            int slot = atomicAdd(&g_nrep, 1);
            g_rep[slot] = n;
        }
    }
}

// ---------------------------------------------------------------------------
// Kernel: flat exact fp32 full rescan (batch of 8 positions per block,
// 8 warps x 128 codewords each; single pass over the codebook).
// ---------------------------------------------------------------------------
__global__ __launch_bounds__(256) void k_rescan(const float* __restrict__ inp) {
    __shared__ float xs[8][260];
    __shared__ int   sn[8];
    const int t = threadIdx.x;
    const int w = t >> 5, lane = t & 31;
    const int nrep = g_nrep;
    const int nbatch = (nrep + 7) >> 3;

    for (int bi = blockIdx.x; bi < nbatch; bi += gridDim.x) {
        const int base = bi * 8;
        if (t < 8) sn[t] = g_rep[min(base + t, nrep - 1)];
        __syncthreads();
        for (int i = t; i < 2048; i += 256) {
            const int pp = i >> 8, c = i & 255;
            const int n = sn[pp];
            xs[pp][c] = inp[(size_t)(n >> 10) * (CDIM * 1024) + (size_t)c * 1024 + (n & 1023)];
        }
        __syncthreads();

        #pragma unroll 1
        for (int ch = 0; ch < 4; ++ch) {
            const int k = w * 128 + ch * 32 + lane;
            const float4* Ep = (const float4*)(g_Et + (size_t)k * CDIM);
            float acc[8];
            #pragma unroll
            for (int r = 0; r < 8; ++r) acc[r] = 0.f;
            #pragma unroll 8
            for (int c4 = 0; c4 < 64; ++c4) {
                const float4 e = Ep[c4];
                #pragma unroll
                for (int r = 0; r < 8; ++r) {
                    const float4 x4 = *(const float4*)&xs[r][c4 * 4];
                    acc[r] = fmaf(x4.x, e.x, acc[r]);
                    acc[r] = fmaf(x4.y, e.y, acc[r]);
                    acc[r] = fmaf(x4.z, e.z, acc[r]);
                    acc[r] = fmaf(x4.w, e.w, acc[r]);
                }
            }
            const float eh = g_esqh[k];
            #pragma unroll
            for (int r = 0; r < 8; ++r) {
                u64 key = pkey(eh - acc[r], (uint32_t)k);
                #pragma unroll
                for (int off = 16; off; off >>= 1) {
                    const u64 o = __shfl_xor_sync(0xffffffffu, key, off);
                    key = min(key, o);
                }
                if (lane == 0) atomicMin(&g_best[sn[r]], key);
            }
        }
        __syncthreads();
    }
}

// ---------------------------------------------------------------------------
// Kernel: unpack rescanned indices
// ---------------------------------------------------------------------------
__global__ void k_repfin() {
    const int nrep = g_nrep;
    for (int i = blockIdx.x * 256 + threadIdx.x; i < nrep; i += gridDim.x * 256) {
        const int n = g_rep[i];
        g_idx[n] = (int)(g_best[n] & 0xFFFFFFFFull);
    }
}

// ---------------------------------------------------------------------------
// Kernel: quantize gather + loss (32 positions/block, smem-staged rows)
// ---------------------------------------------------------------------------
__global__ __launch_bounds__(256) void k_quant(const float* __restrict__ inp,
                                               float* __restrict__ outq) {
    __shared__ float eq[32][257];
    __shared__ int   sidx[32];
    const int t  = threadIdx.x;
    const int n0 = blockIdx.x * 32;
    const int b  = n0 >> 10;
    const int hw0 = n0 & 1023;

    if (t < 32) sidx[t] = g_idx[n0 + t];
    __syncthreads();
    #pragma unroll 1
    for (int j = 0; j < 32; ++j) {
        eq[j][t] = g_Et[(size_t)sidx[j] * CDIM + t];
    }
    __syncthreads();

    const int hw_l = t & 31;
    const int cg   = t >> 5;
    const size_t base = (size_t)b * (CDIM * 1024) + hw0 + hw_l;

    float ls = 0.f;
    #pragma unroll 4
    for (int cb = 0; cb < 32; ++cb) {
        const int c = cb * 8 + cg;
        const size_t a = base + (size_t)c * 1024;
        const float x = inp[a];
        const float e = eq[hw_l][c];
        outq[a] = e;
        const float d = e - x;
        ls = fmaf(d, d, ls);
    }

    __shared__ float red[256];
    red[t] = ls;
    __syncthreads();
    #pragma unroll
    for (int s = 128; s; s >>= 1) {
        if (t < s) red[t] += red[t + s];
        __syncthreads();
    }
    if (t == 0) atomicAdd(&g_loss, red[0]);
}

// ---------------------------------------------------------------------------
// Kernel: onehot + loss scalar
// ---------------------------------------------------------------------------
__global__ void k_onehot(float* __restrict__ d_out) {
    float* oh = d_out + (QELEMS + 1);
    const int t  = threadIdx.x;
    const int r0 = blockIdx.x * 8;
    #pragma unroll
    for (int rr = 0; rr < 8; ++rr) {
        const int n   = r0 + rr;
        const int idx = g_idx[n];
        const size_t base = (size_t)n * KEMB;
        #pragma unroll
        for (int p = 0; p < 4; ++p) {
            const int j = t + p * 256;
            oh[base + j] = (j == idx) ? 1.0f : 0.0f;
        }
    }
    if (blockIdx.x == 0 && t == 0) {
        d_out[QELEMS] = 1.25f * g_loss / (float)QELEMS;
    }
}

// ---------------------------------------------------------------------------
extern "C" void kernel_launch(void* const* d_in, const int* in_sizes, int n_in,
                              void* d_out, int out_size) {
    const float* inp = (const float*)d_in[0];
    const float* emb = (const float*)d_in[1];
    float* out = (float*)d_out;

    cudaFuncSetAttribute(k_mma, cudaFuncAttributeMaxDynamicSharedMemorySize, MMA_SMEM);

    k_prep_embed<<<32, 256>>>(emb);
    k_prep_x<<<1024, 256>>>(inp);
    k_mma<<<256, 256, MMA_SMEM>>>();
    k_rescan<<<148, 256>>>(inp);
    k_repfin<<<16, 256>>>();
    k_quant<<<1024, 256>>>(inp, out);
    k_onehot<<<4096, 256>>>(out);
}

// round 17
// speedup vs baseline: 1.6324x; 1.1384x over previous
#include <cuda_runtime.h>
#include <cuda_fp16.h>
#include <cstdint>

// VQ argmin: 32768 positions x 1024 codewords, C=256.
// inputs [32,256,32,32] f32, embed [256,1024] f32.
// out = concat(quantize_st [8388608], loss [1], onehot [33554432]) f32.
// fp16 HMMA GEMM (R10 epilogue); near-ties (margin < 0.12) get an exact fp32
// full rescan, decomposed as (8-position batch) x (256-codeword quarter).

#define NPOS   32768
#define KEMB   1024
#define CDIM   256
#define QELEMS 8388608

#define REP_THR 0.12f

// ---------------------------------------------------------------------------
// device scratch
// ---------------------------------------------------------------------------
__device__ __align__(256) __half g_Xh[NPOS * CDIM];
__device__ __align__(256) __half g_Eh[KEMB * CDIM];
__device__ __align__(256) float  g_Et[KEMB * CDIM];   // fp32 codebook [k][c]
__device__ float g_esqh[KEMB];
__device__ int   g_idx[NPOS];
__device__ float g_loss;
__device__ int   g_nrep;
__device__ int   g_rep[NPOS];
__device__ unsigned long long g_best[NPOS];

typedef unsigned long long u64;

// ---------------------------------------------------------------------------
// helpers
// ---------------------------------------------------------------------------
__device__ __forceinline__ uint32_t s2u(const void* p) {
    uint32_t a;
    asm("{ .reg .u64 t; cvta.to.shared.u64 t, %1; cvt.u32.u64 %0, t; }" : "=r"(a) : "l"(p));
    return a;
}
__device__ __forceinline__ void cp16(uint32_t s, const void* g) {
    asm volatile("cp.async.cg.shared.global [%0], [%1], 16;" :: "r"(s), "l"(g));
}
__device__ __forceinline__ void cpcommit() { asm volatile("cp.async.commit_group;"); }
template <int N>
__device__ __forceinline__ void cpwait() { asm volatile("cp.async.wait_group %0;" :: "n"(N)); }

__device__ __forceinline__ void ldm_x4(uint32_t& r0, uint32_t& r1, uint32_t& r2, uint32_t& r3,
                                       uint32_t addr) {
    asm volatile("ldmatrix.sync.aligned.m8n8.x4.shared.b16 {%0,%1,%2,%3}, [%4];"
                 : "=r"(r0), "=r"(r1), "=r"(r2), "=r"(r3) : "r"(addr));
}
__device__ __forceinline__ void mma16816(float* d, const uint32_t* a, const uint32_t* b) {
    asm volatile(
        "mma.sync.aligned.m16n8k16.row.col.f32.f16.f16.f32 "
        "{%0,%1,%2,%3}, {%4,%5,%6,%7}, {%8,%9}, {%0,%1,%2,%3};"
        : "+f"(d[0]), "+f"(d[1]), "+f"(d[2]), "+f"(d[3])
        : "r"(a[0]), "r"(a[1]), "r"(a[2]), "r"(a[3]), "r"(b[0]), "r"(b[1]));
}

__device__ __forceinline__ u64 pkey(float v, uint32_t k) {
    uint32_t u = __float_as_uint(v);
    u ^= (u & 0x80000000u) ? 0xFFFFFFFFu : 0x80000000u;
    return ((u64)u << 32) | k;
}

// ---------------------------------------------------------------------------
// Kernel: embed prep — transpose, fp16+fp32 copies, 0.5||e||^2, counter reset
// ---------------------------------------------------------------------------
__global__ void k_prep_embed(const float* __restrict__ src) {
    __shared__ float Xs[32][257];
    const int t = threadIdx.x;
    const int hw0 = blockIdx.x * 32;
    const int lane = t & 31, w = t >> 5;

    #pragma unroll
    for (int i = 0; i < 32; ++i) {
        int c = w + i * 8;
        Xs[lane][c] = src[(size_t)c * 1024 + hw0 + lane];
    }
    __syncthreads();

    #pragma unroll
    for (int rr = 0; rr < 4; ++rr) {
        int r = w * 4 + rr;
        size_t ob = (size_t)(hw0 + r) * CDIM;
        #pragma unroll
        for (int j = 0; j < 8; ++j) {
            int c = lane + 32 * j;
            float x = Xs[r][c];
            g_Eh[ob + c] = __float2half_rn(x);
            g_Et[ob + c] = x;
        }
    }
    if (t < 32) {
        float s2 = 0.f;
        #pragma unroll 8
        for (int c = 0; c < CDIM; ++c) s2 = fmaf(Xs[t][c], Xs[t][c], s2);
        g_esqh[hw0 + t] = 0.5f * s2;
    }
    if (blockIdx.x == 0 && t == 0) { g_loss = 0.f; g_nrep = 0; }
}

// ---------------------------------------------------------------------------
// Kernel: input prep — transpose + fp16 convert. Grid 1024 x 256.
// ---------------------------------------------------------------------------
__global__ void k_prep_x(const float* __restrict__ src) {
    __shared__ float Xs[32][257];
    const int t = threadIdx.x;
    const int s = blockIdx.x >> 5;
    const int hw0 = (blockIdx.x & 31) * 32;
    const int lane = t & 31, w = t >> 5;
    const float* sp = src + (size_t)s * (CDIM * 1024);

    #pragma unroll
    for (int i = 0; i < 32; ++i) {
        int c = w + i * 8;
        Xs[lane][c] = sp[(size_t)c * 1024 + hw0 + lane];
    }
    __syncthreads();

    #pragma unroll
    for (int rr = 0; rr < 4; ++rr) {
        int r = w * 4 + rr;
        size_t ob = ((size_t)s * 1024 + hw0 + r) * CDIM;
        #pragma unroll
        for (int j = 0; j < 8; ++j) {
            int c = lane + 32 * j;
            g_Xh[ob + c] = __float2half_rn(Xs[r][c]);
        }
    }
}

// ---------------------------------------------------------------------------
// Kernel: fp16 HMMA GEMM + top-2 argmin — R10 configuration, unmodified.
// Grid 256: one CTA per 128 positions.
// ---------------------------------------------------------------------------
#define ROWB   80
#define STG_A  (128 * ROWB)
#define STG    (2 * STG_A)
#define NCHUNK 64
#define MMA_SMEM (3 * STG)

__global__ __launch_bounds__(256, 2) void k_mma() {
    extern __shared__ char dsm[];
    const uint32_t sb = s2u(dsm);
    __shared__ float sEsq[1024];
    __shared__ float sv1[4][128];
    __shared__ float sv2[4][128];
    __shared__ int   sk1[4][128];

    const int tid = threadIdx.x;
    const int l   = tid & 31;
    const int wid = tid >> 5;
    const int wm  = wid & 1;
    const int wn  = wid >> 1;

    const int n0 = blockIdx.x * 128;

    for (int i = tid; i < 1024; i += 256) sEsq[i] = g_esqh[i];

    const __half* Ag0 = g_Xh + (size_t)n0 * CDIM;

    auto load_chunk = [&](int ci) {
        const int kb = ci >> 3, c = ci & 7;
        const __half* Ag = Ag0 + c * 32;
        const __half* Bg = g_Eh + (size_t)(kb * 128) * CDIM + c * 32;
        const uint32_t ab = sb + (ci % 3) * STG, bbs = ab + STG_A;
        #pragma unroll
        for (int u = 0; u < 2; ++u) {
            const int idx = tid + u * 256;
            const int row = idx >> 2, q = idx & 3;
            cp16(ab  + row * ROWB + q * 16, Ag + (size_t)row * CDIM + q * 8);
            cp16(bbs + row * ROWB + q * 16, Bg + (size_t)row * CDIM + q * 8);
        }
        cpcommit();
    };

    float rv1 = 3.4e38f, rv2 = 3.4e38f;
    int   rk1 = 0;

    load_chunk(0);
    load_chunk(1);
    load_chunk(2);

    #pragma unroll 1
    for (int kb = 0; kb < 8; ++kb) {
        const int k0 = kb * 128;
        float acc[4][4][4];
        #pragma unroll
        for (int i = 0; i < 4; ++i)
            #pragma unroll
            for (int j = 0; j < 4; ++j)
                #pragma unroll
                for (int r = 0; r < 4; ++r) acc[i][j][r] = 0.f;

        #pragma unroll 1
        for (int c = 0; c < 8; ++c) {
            const int ci = kb * 8 + c;
            if (ci <= NCHUNK - 3)      cpwait<2>();
            else if (ci == NCHUNK - 2) cpwait<1>();
            else                       cpwait<0>();
            __syncthreads();

            const uint32_t ab = sb + (ci % 3) * STG, bbs = ab + STG_A;
            #pragma unroll
            for (int ks = 0; ks < 2; ++ks) {
                uint32_t afr[4][4], bfr[4][2];
                #pragma unroll
                for (int mt = 0; mt < 4; ++mt)
                    ldm_x4(afr[mt][0], afr[mt][1], afr[mt][2], afr[mt][3],
                           ab + (uint32_t)(wm * 64 + mt * 16 + (l & 15)) * ROWB
                              + (uint32_t)(ks * 16 + (l >> 4) * 8) * 2);
                #pragma unroll
                for (int ntp = 0; ntp < 2; ++ntp)
                    ldm_x4(bfr[2 * ntp][0], bfr[2 * ntp][1],
                           bfr[2 * ntp + 1][0], bfr[2 * ntp + 1][1],
                           bbs + (uint32_t)(wn * 32 + ntp * 16 + ((l >> 4) & 1) * 8 + (l & 7)) * ROWB
                               + (uint32_t)(ks * 16 + ((l >> 3) & 1) * 8) * 2);
                #pragma unroll
                for (int mt = 0; mt < 4; ++mt)
                    #pragma unroll
                    for (int nt = 0; nt < 4; ++nt)
                        mma16816(acc[mt][nt], afr[mt], bfr[nt]);
            }
            __syncthreads();
            if (ci + 3 < NCHUNK) load_chunk(ci + 3);
        }

        // ---- epilogue: per-row top-2 (v1,k1,v2) ----
        #pragma unroll
        for (int mt = 0; mt < 4; ++mt) {
            #pragma unroll
            for (int rr = 0; rr < 2; ++rr) {
                const int rowCTA = wm * 64 + mt * 16 + (l >> 2) + rr * 8;
                float v1 = 3.4e38f, v2 = 3.4e38f;
                int   k1 = 0;
                #pragma unroll
                for (int nt = 0; nt < 4; ++nt) {
                    #pragma unroll
                    for (int cc = 0; cc < 2; ++cc) {
                        const int col = wn * 32 + nt * 8 + (l & 3) * 2 + cc;
                        const float v = sEsq[k0 + col] - acc[mt][nt][rr * 2 + cc];
                        if (v < v1)      { v2 = v1; v1 = v; k1 = k0 + col; }
                        else if (v < v2) { v2 = v; }
                    }
                }
                #pragma unroll
                for (int off = 1; off <= 2; off <<= 1) {
                    const float ov1 = __shfl_xor_sync(0xffffffffu, v1, off);
                    const float ov2 = __shfl_xor_sync(0xffffffffu, v2, off);
                    const int   ok1 = __shfl_xor_sync(0xffffffffu, k1, off);
                    if (ov1 < v1 || (ov1 == v1 && ok1 < k1)) {
                        v2 = fminf(v1, ov2); v1 = ov1; k1 = ok1;
                    } else {
                        v2 = fminf(v2, ov1);
                    }
                }
                if ((l & 3) == 0) {
                    sv1[wn][rowCTA] = v1; sv2[wn][rowCTA] = v2; sk1[wn][rowCTA] = k1;
                }
            }
        }
        __syncthreads();
        if (tid < 128) {
            #pragma unroll
            for (int w = 0; w < 4; ++w) {
                const float pv1 = sv1[w][tid], pv2 = sv2[w][tid];
                const int   pk  = sk1[w][tid];
                if (pv1 < rv1 || (pv1 == rv1 && pk < rk1)) {
                    rv2 = fminf(rv1, pv2); rv1 = pv1; rk1 = pk;
                } else {
                    rv2 = fminf(rv2, pv1);
                }
            }
        }
        __syncthreads();
    }

    if (tid < 128) {
        const int n = n0 + tid;
        g_idx[n] = rk1;
        if (rv2 - rv1 < REP_THR) {         // near-tie: exact full rescan
            g_best[n] = 0xFFFFFFFFFFFFFFFFull;
            int slot = atomicAdd(&g_nrep, 1);
            g_rep[slot] = n;
        }
    }
}

// ---------------------------------------------------------------------------
// Kernel: flat exact fp32 rescan, work item = (8-position batch, 256-codeword
// quarter). 8 warps x 32 k each; atomicMin(packed key) merge.
// ---------------------------------------------------------------------------
__global__ __launch_bounds__(256) void k_rescan(const float* __restrict__ inp) {
    __shared__ float xs[8][260];
    __shared__ int   sn[8];
    const int t = threadIdx.x;
    const int w = t >> 5, lane = t & 31;
    const int nrep = g_nrep;
    const int nwork = ((nrep + 7) >> 3) * 4;

    for (int wi = blockIdx.x; wi < nwork; wi += gridDim.x) {
        const int bi = wi >> 2, q = wi & 3;
        const int base = bi * 8;
        if (t < 8) sn[t] = g_rep[min(base + t, nrep - 1)];
        __syncthreads();
        for (int i = t; i < 2048; i += 256) {
            const int pp = i >> 8, c = i & 255;
            const int n = sn[pp];
            xs[pp][c] = inp[(size_t)(n >> 10) * (CDIM * 1024) + (size_t)c * 1024 + (n & 1023)];
        }
        __syncthreads();

        const int k = q * 256 + w * 32 + lane;
        const float4* Ep = (const float4*)(g_Et + (size_t)k * CDIM);
        float acc[8];
        #pragma unroll
        for (int r = 0; r < 8; ++r) acc[r] = 0.f;
        #pragma unroll 8
        for (int c4 = 0; c4 < 64; ++c4) {
            const float4 e = Ep[c4];
            #pragma unroll
            for (int r = 0; r < 8; ++r) {
                const float4 x4 = *(const float4*)&xs[r][c4 * 4];
                acc[r] = fmaf(x4.x, e.x, acc[r]);
                acc[r] = fmaf(x4.y, e.y, acc[r]);
                acc[r] = fmaf(x4.z, e.z, acc[r]);
                acc[r] = fmaf(x4.w, e.w, acc[r]);
            }
        }
        const float eh = g_esqh[k];
        #pragma unroll
        for (int r = 0; r < 8; ++r) {
            u64 key = pkey(eh - acc[r], (uint32_t)k);
            #pragma unroll
            for (int off = 16; off; off >>= 1) {
                const u64 o = __shfl_xor_sync(0xffffffffu, key, off);
                key = min(key, o);
            }
            if (lane == 0) atomicMin(&g_best[sn[r]], key);
        }
        __syncthreads();
    }
}

// ---------------------------------------------------------------------------
// Kernel: unpack rescanned indices
// ---------------------------------------------------------------------------
__global__ void k_repfin() {
    const int nrep = g_nrep;
    for (int i = blockIdx.x * 256 + threadIdx.x; i < nrep; i += gridDim.x * 256) {
        const int n = g_rep[i];
        g_idx[n] = (int)(g_best[n] & 0xFFFFFFFFull);
    }
}

// ---------------------------------------------------------------------------
// Kernel: quantize gather + loss (32 positions/block, smem-staged rows)
// ---------------------------------------------------------------------------
__global__ __launch_bounds__(256) void k_quant(const float* __restrict__ inp,
                                               float* __restrict__ outq) {
    __shared__ float eq[32][257];
    __shared__ int   sidx[32];
    const int t  = threadIdx.x;
    const int n0 = blockIdx.x * 32;
    const int b  = n0 >> 10;
    const int hw0 = n0 & 1023;

    if (t < 32) sidx[t] = g_idx[n0 + t];
    __syncthreads();
    #pragma unroll 1
    for (int j = 0; j < 32; ++j) {
        eq[j][t] = g_Et[(size_t)sidx[j] * CDIM + t];
    }
    __syncthreads();

    const int hw_l = t & 31;
    const int cg   = t >> 5;
    const size_t base = (size_t)b * (CDIM * 1024) + hw0 + hw_l;

    float ls = 0.f;
    #pragma unroll 4
    for (int cb = 0; cb < 32; ++cb) {
        const int c = cb * 8 + cg;
        const size_t a = base + (size_t)c * 1024;
        const float x = inp[a];
        const float e = eq[hw_l][c];
        outq[a] = e;
        const float d = e - x;
        ls = fmaf(d, d, ls);
    }

    __shared__ float red[256];
    red[t] = ls;
    __syncthreads();
    #pragma unroll
    for (int s = 128; s; s >>= 1) {
        if (t < s) red[t] += red[t + s];
        __syncthreads();
    }
    if (t == 0) atomicAdd(&g_loss, red[0]);
}

// ---------------------------------------------------------------------------
// Kernel: onehot + loss scalar
// ---------------------------------------------------------------------------
__global__ void k_onehot(float* __restrict__ d_out) {
    float* oh = d_out + (QELEMS + 1);
    const int t  = threadIdx.x;
    const int r0 = blockIdx.x * 8;
    #pragma unroll
    for (int rr = 0; rr < 8; ++rr) {
        const int n   = r0 + rr;
        const int idx = g_idx[n];
        const size_t base = (size_t)n * KEMB;
        #pragma unroll
        for (int p = 0; p < 4; ++p) {
            const int j = t + p * 256;
            oh[base + j] = (j == idx) ? 1.0f : 0.0f;
        }
    }
    if (blockIdx.x == 0 && t == 0) {
        d_out[QELEMS] = 1.25f * g_loss / (float)QELEMS;
    }
}

// ---------------------------------------------------------------------------
extern "C" void kernel_launch(void* const* d_in, const int* in_sizes, int n_in,
                              void* d_out, int out_size) {
    const float* inp = (const float*)d_in[0];
    const float* emb = (const float*)d_in[1];
    float* out = (float*)d_out;

    cudaFuncSetAttribute(k_mma, cudaFuncAttributeMaxDynamicSharedMemorySize, MMA_SMEM);

    k_prep_embed<<<32, 256>>>(emb);
    k_prep_x<<<1024, 256>>>(inp);
    k_mma<<<256, 256, MMA_SMEM>>>();
    k_rescan<<<592, 256>>>(inp);
    k_repfin<<<16, 256>>>();
    k_quant<<<1024, 256>>>(inp, out);
    k_onehot<<<4096, 256>>>(out);
}